// round 5
// baseline (speedup 1.0000x reference)
#include <cuda_runtime.h>
#include <math.h>

#define NMAX 10000
#define EMAX 320000

// ---------------- scratch (device globals; no allocation allowed) -------------
__device__ int      g_is64;
__device__ float    g_deg[NMAX];
__device__ float    g_dis[NMAX];
__device__ int      g_cnt[NMAX];
__device__ int      g_rowptr[NMAX + 1];
__device__ int      g_srcd[EMAX];
__device__ int      g_dstd[EMAX];
__device__ int2     g_colw[EMAX];          // packed (src col, bitcast norm)
__device__ unsigned g_arrive;
__device__ volatile unsigned g_gen;
__device__ __align__(256) float g_h[NMAX * 64];
__device__ __align__(256) float g_acc[NMAX * 64];
__device__ __align__(256) float g_B0[NMAX * 64];
__device__ __align__(256) float g_B1[NMAX * 64];
__device__ __align__(256) float g_B2[NMAX * 64];

constexpr int TPB = 256;
constexpr int NPB = 8;   // nodes per block-pass (one per warp)

// ---------------- software grid barrier (grid sized for co-residency) ---------
__device__ __forceinline__ void gbar(int G) {
    __syncthreads();
    if (threadIdx.x == 0) {
        __threadfence();
        unsigned gen = g_gen;
        if (atomicAdd(&g_arrive, 1u) == (unsigned)G - 1u) {
            g_arrive = 0u;
            __threadfence();
            g_gen = gen + 1u;   // release
        } else {
            while (g_gen == gen) { __nanosleep(64); }
            __threadfence();
        }
    }
    __syncthreads();
}

// ---------------- preprocessing (math proven in rounds 3/4) -------------------
__global__ void zero_detect_k(const int* __restrict__ ei32, int E, int n) {
    int i = blockIdx.x * blockDim.x + threadIdx.x;
    if (i < n) {
        g_deg[i] = 0.f;
        g_cnt[i] = 0;
    }
    if (i == 0) { g_arrive = 0u; g_gen = 0u; }
    if (blockIdx.x == 0) {
        // int64 layout iff every odd 32-bit word is 0 over the sample
        __shared__ int bad;
        if (threadIdx.x == 0) bad = 0;
        __syncthreads();
        int nsamp = E / 2;
        if (nsamp > 4096) nsamp = 4096;
        for (int t = threadIdx.x; t < nsamp; t += blockDim.x)
            if (ei32[2 * t + 1] != 0) bad = 1;
        __syncthreads();
        if (threadIdx.x == 0) g_is64 = (bad == 0) ? 1 : 0;
    }
}

__global__ void prep_edges_k(const void* __restrict__ ei,
                             const float* __restrict__ w, int E, int n) {
    int e = blockIdx.x * blockDim.x + threadIdx.x;
    if (e >= E) return;
    int s, d;
    if (g_is64) {
        const long long* p = (const long long*)ei;
        s = (int)p[e];
        d = (int)p[(long long)E + e];
    } else {
        const int* p = (const int*)ei;
        s = p[e];
        d = p[E + e];
    }
    s = (s < 0) ? 0 : ((s >= n) ? n - 1 : s);
    d = (d < 0) ? 0 : ((d >= n) ? n - 1 : d);
    g_srcd[e] = s;
    g_dstd[e] = d;
    atomicAdd(&g_deg[s], w[e]);
    atomicAdd(&g_cnt[d], 1);
}

// single block: dis for all nodes, then exclusive scan of cnt -> rowptr
__global__ void dis_scan_k(int n) {
    __shared__ int ssum[1024];
    int t = threadIdx.x;
    for (int i = t; i < n; i += 1024) {
        float d = g_deg[i];
        g_dis[i] = (d > 0.f) ? (1.f / sqrtf(d)) : 0.f;
    }
    __syncthreads();
    int chunk = (n + 1023) / 1024;
    int beg = t * chunk;
    int end = beg + chunk;
    if (beg > n) beg = n;
    if (end > n) end = n;
    int s = 0;
    for (int i = beg; i < end; i++) s += g_cnt[i];
    ssum[t] = s;
    __syncthreads();
    for (int off = 1; off < 1024; off <<= 1) {
        int v = (t >= off) ? ssum[t - off] : 0;
        __syncthreads();
        ssum[t] += v;
        __syncthreads();
    }
    int run = (t == 0) ? 0 : ssum[t - 1];
    for (int i = beg; i < end; i++) {
        int c = g_cnt[i];
        g_rowptr[i] = run;
        g_cnt[i] = run;   // cursor for scatter
        run += c;
    }
    if (t == 1023) g_rowptr[n] = ssum[1023];
}

__global__ void scatter_k(const float* __restrict__ w, int E) {
    int e = blockIdx.x * blockDim.x + threadIdx.x;
    if (e >= E) return;
    int s = g_srcd[e], d = g_dstd[e];
    float nv = -g_dis[s] * w[e] * g_dis[d];
    int p = atomicAdd(&g_cnt[d], 1);
    g_colw[p] = make_int2(s, __float_as_int(nv));
}

// ---------------- persistent layer kernel ------------------------------------
// Runs all K Chebyshev steps with an internal grid barrier between steps.
// Per step k: T_k computed into Ts (smem) per node, written to dst buffer,
// then block GEMM acc (+)= T_k @ W_k (+ bias at k=0).
template <int IN, int OUT>
__global__ __launch_bounds__(TPB)
void layer_persist(const float* __restrict__ h0,
                   float* __restrict__ acc,
                   float* __restrict__ B0,
                   float* __restrict__ B1,
                   float* __restrict__ B2,
                   const float* __restrict__ W,
                   const float* __restrict__ bias,
                   int n, int K, int G) {
    constexpr int PAD = (IN % 16 == 0) ? 0 : 1;
    __shared__ __align__(16) float Ts[NPB][IN + PAD];
    __shared__ float Ws[IN * OUT];

    int tid  = threadIdx.x;
    int wrp  = tid >> 5;
    int lane = tid & 31;

    const float* src = h0;      // T_{k-1}
    const float* prv = nullptr; // T_{k-2}
    float* bufs0 = B1; float* bufs1 = B2; float* bufs2 = B0;

    int tiles = (n + G * NPB - 1) / (G * NPB);

    for (int k = 0; k < K; k++) {
        // stage W_k (previous step's readers are past gbar's syncthreads)
        for (int i = tid; i < IN * OUT; i += TPB) Ws[i] = W[k * IN * OUT + i];

        float* dst = nullptr;
        if (k >= 1) {
            int r = (k - 1) % 3;
            dst = (r == 0) ? bufs0 : (r == 1) ? bufs1 : bufs2;
        }

        for (int p = 0; p < tiles; p++) {
            int base = (p * G + blockIdx.x) * NPB;
            int nd = base + wrp;
            if (nd < n) {
                if (k == 0) {
                    for (int f = lane; f < IN; f += 32) Ts[wrp][f] = h0[nd * IN + f];
                } else if (IN == 4) {
                    // lane-per-edge float4 gather
                    int beg = g_rowptr[nd], end = g_rowptr[nd + 1];
                    float4 s = make_float4(0.f, 0.f, 0.f, 0.f);
                    for (int e = beg + lane; e < end; e += 32) {
                        int2 cw = __ldg(&g_colw[e]);
                        float nv = __int_as_float(cw.y);
                        float4 v = __ldg((const float4*)(src + cw.x * 4));
                        s.x += nv * v.x; s.y += nv * v.y;
                        s.z += nv * v.z; s.w += nv * v.w;
                    }
#pragma unroll
                    for (int off = 16; off >= 1; off >>= 1) {
                        s.x += __shfl_xor_sync(0xffffffffu, s.x, off);
                        s.y += __shfl_xor_sync(0xffffffffu, s.y, off);
                        s.z += __shfl_xor_sync(0xffffffffu, s.z, off);
                        s.w += __shfl_xor_sync(0xffffffffu, s.w, off);
                    }
                    if (lane == 0) {
                        float4 t = s;
                        if (k >= 2) {
                            float4 q = __ldg((const float4*)(prv + nd * 4));
                            t.x = 2.f * s.x - q.x; t.y = 2.f * s.y - q.y;
                            t.z = 2.f * s.z - q.z; t.w = 2.f * s.w - q.w;
                        }
                        *((float4*)(dst + nd * 4)) = t;
                        Ts[wrp][0] = t.x; Ts[wrp][1] = t.y;
                        Ts[wrp][2] = t.z; Ts[wrp][3] = t.w;
                    }
                } else if (IN % 16 == 0) {
                    // half-warp per edge, float4 per lane, unrolled x2 for MLP
                    int beg = g_rowptr[nd], end = g_rowptr[nd + 1];
                    int half = lane >> 4;
                    int fl   = lane & 15;
                    float4 sA = make_float4(0.f, 0.f, 0.f, 0.f);
                    float4 sB = make_float4(0.f, 0.f, 0.f, 0.f);
                    int e = beg + half;
                    for (; e + 2 < end; e += 4) {
                        int2 cw0 = __ldg(&g_colw[e]);
                        int2 cw1 = __ldg(&g_colw[e + 2]);
                        float4 v0 = __ldg(((const float4*)(src + cw0.x * IN)) + fl);
                        float4 v1 = __ldg(((const float4*)(src + cw1.x * IN)) + fl);
                        float n0 = __int_as_float(cw0.y);
                        float n1 = __int_as_float(cw1.y);
                        sA.x += n0 * v0.x; sA.y += n0 * v0.y;
                        sA.z += n0 * v0.z; sA.w += n0 * v0.w;
                        sB.x += n1 * v1.x; sB.y += n1 * v1.y;
                        sB.z += n1 * v1.z; sB.w += n1 * v1.w;
                    }
                    for (; e < end; e += 2) {
                        int2 cw = __ldg(&g_colw[e]);
                        float nv = __int_as_float(cw.y);
                        float4 v = __ldg(((const float4*)(src + cw.x * IN)) + fl);
                        sA.x += nv * v.x; sA.y += nv * v.y;
                        sA.z += nv * v.z; sA.w += nv * v.w;
                    }
                    float4 s = make_float4(sA.x + sB.x, sA.y + sB.y,
                                           sA.z + sB.z, sA.w + sB.w);
                    s.x += __shfl_xor_sync(0xffffffffu, s.x, 16);
                    s.y += __shfl_xor_sync(0xffffffffu, s.y, 16);
                    s.z += __shfl_xor_sync(0xffffffffu, s.z, 16);
                    s.w += __shfl_xor_sync(0xffffffffu, s.w, 16);
                    if (lane < 16) {
                        float4 t = s;
                        if (k >= 2) {
                            float4 q = __ldg(((const float4*)(prv + nd * IN)) + fl);
                            t.x = 2.f * s.x - q.x; t.y = 2.f * s.y - q.y;
                            t.z = 2.f * s.z - q.z; t.w = 2.f * s.w - q.w;
                        }
                        ((float4*)(dst + nd * IN))[fl] = t;
                        ((float4*)(&Ts[wrp][0]))[fl] = t;
                    }
                } else {
                    // odd width (IN=60): lane-per-feature scalar path
                    int beg = g_rowptr[nd], end = g_rowptr[nd + 1];
                    int f0 = lane, f1 = lane + 32;
                    float s0 = 0.f, s1 = 0.f;
                    for (int e = beg; e < end; e++) {
                        int2 cw = __ldg(&g_colw[e]);
                        float nv = __int_as_float(cw.y);
                        const float* rp = src + cw.x * IN;
                        s0 += nv * __ldg(&rp[f0]);
                        if (f1 < IN) s1 += nv * __ldg(&rp[f1]);
                    }
                    {
                        float t0 = (k >= 2) ? 2.f * s0 - prv[nd * IN + f0] : s0;
                        dst[nd * IN + f0] = t0;
                        Ts[wrp][f0] = t0;
                    }
                    if (f1 < IN) {
                        float t1 = (k >= 2) ? 2.f * s1 - prv[nd * IN + f1] : s1;
                        dst[nd * IN + f1] = t1;
                        Ts[wrp][f1] = t1;
                    }
                }
            }
            __syncthreads();

            // block GEMM: acc[node, j] (+)= sum_i Ts[node][i] * Ws[i][j]
            constexpr int JS     = (OUT > 32) ? 64 : 32;
            constexpr int GROUPS = TPB / JS;
            constexpr int NPG    = NPB / GROUPS;
            int j = tid % JS;
            int g = tid / JS;
            if (j < OUT) {
                float a[NPG];
#pragma unroll
                for (int q = 0; q < NPG; q++) a[q] = 0.f;
#pragma unroll 4
                for (int i = 0; i < IN; i++) {
                    float wv = Ws[i * OUT + j];
#pragma unroll
                    for (int q = 0; q < NPG; q++) a[q] += wv * Ts[g * NPG + q][i];
                }
#pragma unroll
                for (int q = 0; q < NPG; q++) {
                    int node = base + g * NPG + q;
                    if (node < n) {
                        if (k == 0)
                            acc[node * OUT + j] = a[q] + bias[j];
                        else
                            acc[node * OUT + j] += a[q];
                    }
                }
            }
            __syncthreads();
        }

        if (k >= 1) { prv = src; src = dst; }
        gbar(G);   // T_k fully written & acc updated before step k+1 gathers
    }
}

// ---------------- epilogues --------------------------------------------------
__global__ void silu_k(const float* __restrict__ a, float* __restrict__ h, int cnt) {
    int i = blockIdx.x * blockDim.x + threadIdx.x;
    if (i < cnt) {
        float v = a[i];
        h[i] = v / (1.f + expf(-v));
    }
}

__global__ void final_k(const float* __restrict__ h, const float* __restrict__ W4,
                        float* __restrict__ out, int n) {
    int i = blockIdx.x * blockDim.x + threadIdx.x;
    if (i < n) {
        float s = 0.f;
#pragma unroll
        for (int k = 0; k < 30; k++) s += h[i * 30 + k] * W4[k];
        out[i] = 1.f / (1.f + expf(-s));
    }
}

// ---------------- host orchestration -----------------------------------------
template <int IN, int OUT>
static int grid_for() {
    static int cached = 0;
    if (cached) return cached;
    int dev = 0;
    cudaGetDevice(&dev);
    int sms = 0;
    cudaDeviceGetAttribute(&sms, cudaDevAttrMultiProcessorCount, dev);
    int bps = 0;
    cudaOccupancyMaxActiveBlocksPerMultiprocessor(&bps, layer_persist<IN, OUT>, TPB, 0);
    if (sms <= 0) sms = 148;
    if (bps <= 0) bps = 1;
    if (bps > 8) bps = 8;
    cached = sms * bps;
    return cached;
}

extern "C" void kernel_launch(void* const* d_in, const int* in_sizes, int n_in,
                              void* d_out, int out_size) {
    const float* x  = (const float*)d_in[0];
    const void*  ei = d_in[1];
    const float* ew = (const float*)d_in[2];
    const float* W1 = (const float*)d_in[3];
    const float* b1 = (const float*)d_in[4];
    const float* W2 = (const float*)d_in[5];
    const float* b2 = (const float*)d_in[6];
    const float* W3 = (const float*)d_in[7];
    const float* b3 = (const float*)d_in[8];
    const float* W4 = (const float*)d_in[9];
    float* out = (float*)d_out;

    int n = in_sizes[0] / 4;   // 10000
    int E = in_sizes[2];       // 320000

    float *p_h, *p_acc, *p_B0, *p_B1, *p_B2;
    cudaGetSymbolAddress((void**)&p_h,   g_h);
    cudaGetSymbolAddress((void**)&p_acc, g_acc);
    cudaGetSymbolAddress((void**)&p_B0,  g_B0);
    cudaGetSymbolAddress((void**)&p_B1,  g_B1);
    cudaGetSymbolAddress((void**)&p_B2,  g_B2);

    // preprocessing: degrees + CSR by dst (4 launches)
    int eb = (E + TPB - 1) / TPB;
    zero_detect_k<<<(n + TPB - 1) / TPB, TPB>>>((const int*)ei, E, n);
    prep_edges_k<<<eb, TPB>>>(ei, ew, E, n);
    dis_scan_k<<<1, 1024>>>(n);
    scatter_k<<<eb, TPB>>>(ew, E);

    // layer 1: ChebConv(4 -> 64, K=120) + SiLU
    {
        int G = grid_for<4, 64>();
        layer_persist<4, 64><<<G, TPB>>>(x, p_acc, p_B0, p_B1, p_B2, W1, b1,
                                         n, 120, G);
        silu_k<<<(n * 64 + TPB - 1) / TPB, TPB>>>(p_acc, p_h, n * 64);
    }
    // layer 2: ChebConv(64 -> 60, K=120) + SiLU
    {
        int G = grid_for<64, 60>();
        layer_persist<64, 60><<<G, TPB>>>(p_h, p_acc, p_B0, p_B1, p_B2, W2, b2,
                                          n, 120, G);
        silu_k<<<(n * 60 + TPB - 1) / TPB, TPB>>>(p_acc, p_h, n * 60);
    }
    // layer 3: ChebConv(60 -> 30, K=20) + SiLU
    {
        int G = grid_for<60, 30>();
        layer_persist<60, 30><<<G, TPB>>>(p_h, p_acc, p_B0, p_B1, p_B2, W3, b3,
                                          n, 20, G);
        silu_k<<<(n * 30 + TPB - 1) / TPB, TPB>>>(p_acc, p_h, n * 30);
    }
    // layer 4: ChebConv(30 -> 1, K=1) + sigmoid
    final_k<<<(n + TPB - 1) / TPB, TPB>>>(p_h, W4, out, n);
}